// round 1
// baseline (speedup 1.0000x reference)
#include <cuda_runtime.h>
#include <math.h>

#define HFD 64
#define WFD 64
#define CIN 1280
#define CCAP 256
#define NCAPS 19
#define DK 64
#define DV 16
#define NP 96              // padded cols: 0..63 K-proj, 64..79 V-proj, 80 act-logit, 81..95 zero
#define BATCH 8
#define NINST 32
#define NPTS 256
#define NPIX (HFD*WFD)     // 4096

// scratch (no cudaMalloc allowed)
__device__ float g_Wfold[CIN*NP];     // 491 KB
__device__ float g_const[NP];
__device__ float g_pk[BATCH*NPIX*NP]; // 12.6 MB

// ---------------- kernel 0a: fold Wp into Wk/Wv; Wa row 0 as col 80 ----------------
__global__ void fold_kernel(const float* __restrict__ Wp, const float* __restrict__ Wa,
                            const float* __restrict__ Wk, const float* __restrict__ Wv) {
    __shared__ float wp[CCAP];
    int c = blockIdx.x;
    int t = threadIdx.x;     // 0..95
    for (int j = t; j < CCAP; j += 96) wp[j] = Wp[j*CIN + c];
    __syncthreads();
    float s = 0.f;
    if (t < DK) {
        #pragma unroll 4
        for (int j = 0; j < CCAP; ++j) s += wp[j]*Wk[j*DK + t];
    } else if (t < 80) {
        int o = t - 64;
        #pragma unroll 4
        for (int j = 0; j < CCAP; ++j) s += wp[j]*Wv[j*DV + o];
    } else if (t == 80) {
        s = Wa[c];           // row 0 of Wa [256,1280]
    }
    g_Wfold[c*NP + t] = s;
}

// ---------------- kernel 0b: fold biases ----------------
__global__ void const_kernel(const float* __restrict__ bp, const float* __restrict__ ba,
                             const float* __restrict__ Wk, const float* __restrict__ bk,
                             const float* __restrict__ Wv, const float* __restrict__ bv) {
    int t = threadIdx.x;     // 0..95
    float s = 0.f;
    if (t < DK) {
        s = bk[t];
        for (int j = 0; j < CCAP; ++j) s += bp[j]*Wk[j*DK + t];
    } else if (t < 80) {
        int o = t - 64;
        s = bv[o];
        for (int j = 0; j < CCAP; ++j) s += bp[j]*Wv[j*DV + o];
    } else if (t == 80) {
        s = ba[0];
    }
    g_const[t] = s;
}

// ---------------- kernel 1: pk = feat @ Wfold + const  ([32768 x 1280] x [1280 x 96]) ----------------
#define BM 128
#define BN 96
#define BK 16
#define TM 8
#define TN 6

__global__ __launch_bounds__(256) void gemm_kernel(const float* __restrict__ feat) {
    __shared__ float As[BK][BM];
    __shared__ float Bs[BK][BN];
    int t  = threadIdx.x;
    int m0 = blockIdx.x * BM;
    int b  = m0 / NPIX;                 // BM divides NPIX, so constant per block
    int pix0 = m0 % NPIX;
    const float* aBase = feat + (size_t)b*CIN*NPIX + pix0;

    int tx = t % 16;                    // N direction (16 * TN = 96)
    int ty = t / 16;                    // M direction (16 * TM = 128)
    float acc[TM][TN];
    #pragma unroll
    for (int i = 0; i < TM; i++)
        #pragma unroll
        for (int j = 0; j < TN; j++) acc[i][j] = 0.f;

    int lm  = t % BM;                   // 0..127
    int lk0 = t / BM;                   // 0 or 1

    for (int k0 = 0; k0 < CIN; k0 += BK) {
        #pragma unroll
        for (int i = 0; i < 8; i++) {
            int kk = lk0 + 2*i;
            As[kk][lm] = aBase[(size_t)(k0+kk)*NPIX + lm];
        }
        #pragma unroll
        for (int i = 0; i < 6; i++) {
            int idx = t + 256*i;        // 1536 elems
            int kk = idx / BN;
            int o  = idx % BN;
            Bs[kk][o] = g_Wfold[(k0+kk)*NP + o];
        }
        __syncthreads();
        #pragma unroll
        for (int kk = 0; kk < BK; ++kk) {
            float a[TM], bb[TN];
            #pragma unroll
            for (int i = 0; i < TM; i++) a[i]  = As[kk][ty*TM + i];
            #pragma unroll
            for (int j = 0; j < TN; j++) bb[j] = Bs[kk][tx*TN + j];
            #pragma unroll
            for (int i = 0; i < TM; i++)
                #pragma unroll
                for (int j = 0; j < TN; j++)
                    acc[i][j] += a[i]*bb[j];
        }
        __syncthreads();
    }
    #pragma unroll
    for (int i = 0; i < TM; i++) {
        int m = m0 + ty*TM + i;
        #pragma unroll
        for (int j = 0; j < TN; j++) {
            int o = tx*TN + j;
            g_pk[(size_t)m*NP + o] = acc[i][j] + g_const[o];
        }
    }
}

// ---------------- kernel 2: dedupe + routing attention, one block per (b, instance) ----------------
__global__ __launch_bounds__(256) void route_kernel(
    const int* __restrict__ pts,        // [B, NI, 2, P] int32
    const float* __restrict__ Q,        // [19,64]
    const float* __restrict__ Wk,       // [258,64]
    const float* __restrict__ Wv,       // [258,16]
    const float* __restrict__ Wl,       // [16,1]
    const float* __restrict__ bl,       // [1]
    float* __restrict__ out)            // [B, NI, 19]
{
    __shared__ float Qs[NCAPS*DK];
    __shared__ unsigned bitmap[NPIX/32];          // 128 words
    __shared__ int counts[NPIX/32];
    __shared__ int offs[NPIX/32 + 1];
    __shared__ unsigned short cells[NPTS];
    __shared__ int sumY, sumX;
    __shared__ float scores[NCAPS][NPTS];
    __shared__ float vmatS[DV][NPTS];
    __shared__ float relK[2][DK];
    __shared__ float relV[2][DV];
    __shared__ float Wls[DV];

    int t  = threadIdx.x;
    int bi = blockIdx.x;                 // b*NI + i
    const int* pbase = pts + (size_t)bi*2*NPTS;

    for (int i = t; i < NCAPS*DK; i += 256) Qs[i] = Q[i];
    if (t < NPIX/32) bitmap[t] = 0u;
    if (t < DK) { relK[0][t] = Wk[256*DK + t]; relK[1][t] = Wk[257*DK + t]; }
    if (t < DV) { relV[0][t] = Wv[256*DV + t]; relV[1][t] = Wv[257*DV + t]; Wls[t] = Wl[t]; }
    if (t == 0) { sumY = 0; sumX = 0; }
    __syncthreads();

    // mark unique cells
    {
        int y = pbase[t] >> 4;           // pts // 16 (coords are non-negative)
        int x = pbase[NPTS + t] >> 4;
        int key = y*WFD + x;
        atomicOr(&bitmap[key >> 5], 1u << (key & 31));
    }
    __syncthreads();
    if (t < NPIX/32) counts[t] = __popc(bitmap[t]);
    __syncthreads();
    if (t == 0) {                        // deterministic exclusive scan (sorted cell order)
        int r = 0;
        for (int i = 0; i < NPIX/32; ++i) { offs[i] = r; r += counts[i]; }
        offs[NPIX/32] = r;
    }
    __syncthreads();
    if (t < NPIX/32) {
        unsigned bits = bitmap[t];
        int idx = offs[t];
        int sy = 0, sx = 0;
        while (bits) {
            int bpos = __ffs(bits) - 1;
            bits &= bits - 1;
            int cell = t*32 + bpos;
            cells[idx++] = (unsigned short)cell;
            sy += cell >> 6;
            sx += cell & 63;
        }
        if (sy | sx | counts[t]) { atomicAdd(&sumY, sy); atomicAdd(&sumX, sx); }
    }
    __syncthreads();

    int U = offs[NPIX/32];
    float nfl = (float)(U > 0 ? U : 1);
    float meanY = (float)sumY / nfl;
    float meanX = (float)sumX / nfl;

    // per-unique-cell: kvec, vmat, scores
    if (t < U) {
        int cell = cells[t];
        const float* pk = &g_pk[((size_t)(bi >> 5)*NPIX + cell)*NP];   // b = bi / 32
        float ry = ((float)(cell >> 6) - meanY) * (1.f/HFD);
        float rx = ((float)(cell & 63) - meanX) * (1.f/WFD);
        float kvec[DK];
        #pragma unroll
        for (int o = 0; o < DK; o++) kvec[o] = pk[o] + ry*relK[0][o] + rx*relK[1][o];
        #pragma unroll
        for (int d = 0; d < DV; d++) vmatS[d][t] = pk[DK + d] + ry*relV[0][d] + rx*relV[1][d];
        float act = 1.f/(1.f + expf(-pk[80]));
        float la  = logf(act + 1e-6f);
        #pragma unroll 1
        for (int c = 0; c < NCAPS; c++) {
            float s = 0.f;
            #pragma unroll
            for (int o = 0; o < DK; o++) s += Qs[c*DK + o]*kvec[o];
            scores[c][t] = s*0.125f + la;      // 1/sqrt(64)
        }
    }
    __syncthreads();

    // softmax + attn @ vmat + logistic, warp per cap
    int warp = t >> 5, lane = t & 31;
    for (int c = warp; c < NCAPS; c += 8) {
        float mx = -1e30f;
        for (int j = lane; j < U; j += 32) mx = fmaxf(mx, scores[c][j]);
        #pragma unroll
        for (int off = 16; off; off >>= 1) mx = fmaxf(mx, __shfl_xor_sync(0xffffffffu, mx, off));
        float se = 0.f;
        float acc[DV];
        #pragma unroll
        for (int d = 0; d < DV; d++) acc[d] = 0.f;
        for (int j = lane; j < U; j += 32) {
            float e = expf(scores[c][j] - mx);
            se += e;
            #pragma unroll
            for (int d = 0; d < DV; d++) acc[d] += e*vmatS[d][j];
        }
        #pragma unroll
        for (int off = 16; off; off >>= 1) {
            se += __shfl_xor_sync(0xffffffffu, se, off);
            #pragma unroll
            for (int d = 0; d < DV; d++) acc[d] += __shfl_xor_sync(0xffffffffu, acc[d], off);
        }
        if (lane == 0) {
            float o = bl[0];
            float inv = 1.f/se;
            #pragma unroll
            for (int d = 0; d < DV; d++) o += (acc[d]*inv)*Wls[d];
            out[bi*NCAPS + c] = 1.f/(1.f + expf(-o));
        }
    }
}

extern "C" void kernel_launch(void* const* d_in, const int* in_sizes, int n_in,
                              void* d_out, int out_size) {
    const float* feat = (const float*)d_in[0];
    const float* Wp   = (const float*)d_in[1];
    const float* bp   = (const float*)d_in[2];
    const float* Wa   = (const float*)d_in[3];
    const float* ba   = (const float*)d_in[4];
    const float* Q    = (const float*)d_in[5];
    const float* Wk   = (const float*)d_in[6];
    const float* bk   = (const float*)d_in[7];
    const float* Wv   = (const float*)d_in[8];
    const float* bv   = (const float*)d_in[9];
    const float* Wl   = (const float*)d_in[10];
    const float* bl   = (const float*)d_in[11];
    const int*   pts  = (const int*)d_in[12];
    float* out = (float*)d_out;

    fold_kernel<<<CIN, 96>>>(Wp, Wa, Wk, Wv);
    const_kernel<<<1, 96>>>(bp, ba, Wk, bk, Wv, bv);
    gemm_kernel<<<(BATCH*NPIX)/BM, 256>>>(feat);
    route_kernel<<<BATCH*NINST, 256>>>(pts, Q, Wk, Wv, Wl, bl, out);
}

// round 2
// speedup vs baseline: 1.9398x; 1.9398x over previous
#include <cuda_runtime.h>
#include <math.h>
#include <stdint.h>

#define HFD 64
#define WFD 64
#define CIN 1280
#define CCAP 256
#define NCAPS 19
#define DK 64
#define DV 16
#define NP 48              // 0..18 score-base, 19 act-logit, 20..35 V, 36..47 zero pad
#define BATCH 8
#define NINST 32
#define NPTS 256
#define NPIX (HFD*WFD)     // 4096

// ---- device scratch (no cudaMalloc allowed) ----
__device__ float    g_QW[NCAPS*258];          // 0.125 * Q @ Wk^T   [19,258]
__device__ uint32_t g_Wf_hi[CIN*NP];          // folded weights, tf32 hi
__device__ uint32_t g_Wf_lo[CIN*NP];          // tf32 lo residual
__device__ float    g_const[NP];
__device__ float    g_pk[BATCH*NPIX*NP];      // 6.3 MB

__device__ __forceinline__ uint32_t f2tf32(float x) {
    uint32_t r; asm("cvt.rna.tf32.f32 %0, %1;" : "=r"(r) : "f"(x)); return r;
}

// ================= kernel A: QW = 0.125 * Q @ Wk^T  [19 x 258] =================
__global__ void qw_kernel(const float* __restrict__ Q, const float* __restrict__ Wk) {
    int idx = blockIdx.x * 256 + threadIdx.x;
    if (idx >= NCAPS*258) return;
    int c = idx / 258, j = idx % 258;
    float s = 0.f;
    #pragma unroll 8
    for (int o = 0; o < DK; ++o) s += Q[c*DK + o] * Wk[j*DK + o];
    g_QW[idx] = 0.125f * s;
}

// ================= kernel B: fold Wp into [QW-score | act | V] cols, tf32 split =================
__global__ void fold_kernel(const float* __restrict__ Wp, const float* __restrict__ Wa,
                            const float* __restrict__ Wv) {
    __shared__ float wp[CCAP];
    int c = blockIdx.x;
    int t = threadIdx.x;                 // 0..63
    for (int j = t; j < CCAP; j += 64) wp[j] = Wp[j*CIN + c];
    __syncthreads();
    if (t >= NP) return;
    float s = 0.f;
    if (t < NCAPS) {
        #pragma unroll 4
        for (int j = 0; j < CCAP; ++j) s += wp[j] * g_QW[t*258 + j];
    } else if (t == NCAPS) {
        s = Wa[c];
    } else if (t < 20 + DV) {
        int o = t - 20;
        #pragma unroll 4
        for (int j = 0; j < CCAP; ++j) s += wp[j] * Wv[j*DV + o];
    }
    uint32_t hi = f2tf32(s);
    float lo = s - __uint_as_float(hi);
    g_Wf_hi[c*NP + t] = hi;
    g_Wf_lo[c*NP + t] = f2tf32(lo);
}

// ================= kernel C: fold biases =================
__global__ void const_kernel(const float* __restrict__ bp, const float* __restrict__ ba,
                             const float* __restrict__ Q,  const float* __restrict__ bk,
                             const float* __restrict__ Wv, const float* __restrict__ bv) {
    int t = threadIdx.x;                 // 0..47
    float s = 0.f;
    if (t < NCAPS) {
        for (int j = 0; j < CCAP; ++j) s += bp[j] * g_QW[t*258 + j];
        float qb = 0.f;
        for (int o = 0; o < DK; ++o) qb += Q[t*DK + o] * bk[o];
        s += 0.125f * qb;
    } else if (t == NCAPS) {
        s = ba[0];
    } else if (t < 20 + DV) {
        int o = t - 20;
        s = bv[o];
        for (int j = 0; j < CCAP; ++j) s += bp[j] * Wv[j*DV + o];
    }
    g_const[t] = s;
}

// ================= kernel 1: GEMM  pk[32768 x 48] = feat[32768 x 1280] @ Wfold =================
// 3xTF32 mma.sync.m16n8k8, BM=128, BN=48, BK=16, 8 warps (each warp: 16 rows x 48 cols)
#define BM 128
#define BK 16
#define AS_STRIDE 136
#define BS_STRIDE 56
#define NKCH (CIN/BK)      // 80

#define CP_ASYNC16(dst_s32, src) \
    asm volatile("cp.async.cg.shared.global [%0], [%1], 16;\n" :: "r"(dst_s32), "l"(src))
#define CP_COMMIT() asm volatile("cp.async.commit_group;\n")

__device__ __forceinline__ void mma_tf32(float* d, const uint32_t* a, uint32_t b0, uint32_t b1) {
    asm volatile(
        "mma.sync.aligned.m16n8k8.row.col.f32.tf32.tf32.f32 "
        "{%0,%1,%2,%3},{%4,%5,%6,%7},{%8,%9},{%0,%1,%2,%3};\n"
        : "+f"(d[0]), "+f"(d[1]), "+f"(d[2]), "+f"(d[3])
        : "r"(a[0]), "r"(a[1]), "r"(a[2]), "r"(a[3]), "r"(b0), "r"(b1));
}

// smem float layout (union):
//   As   : 2 bufs x 16 x 136  at [0, 4352)
//   Bhi  : 2 bufs x 16 x 56   at [4352, 6144)
//   Blo  : 2 bufs x 16 x 56   at [6144, 7936)
//   Cs   : 128 x 48           at [0, 6144)   (after mainloop)
//   csts : 48                 at [7936, 7984)
__global__ __launch_bounds__(256) void gemm_kernel(const float* __restrict__ feat) {
    __shared__ __align__(16) float smem[7984];
    int t = threadIdx.x;
    int m0 = blockIdx.x * BM;
    int b  = m0 / NPIX;
    int pix0 = m0 % NPIX;
    const float* aBase = feat + (size_t)b*CIN*NPIX + pix0;

    if (t < NP) smem[7936 + t] = g_const[t];

    int lane = t & 31, w = t >> 5;
    int gid = lane >> 2, tig = lane & 3;
    int wm = w * 16;

    uint32_t s_as  = (uint32_t)__cvta_generic_to_shared(smem);
    uint32_t s_bhi = s_as + 4352*4;
    uint32_t s_blo = s_as + 6144*4;

    // per-thread load coords
    int a_kk0 = t >> 5;              // first of two A float4 loads: i = t -> kk=t/32
    int a_m0  = (t & 31) * 4;
    int b_kk  = t / 12;              // B loads: t<192
    int b_n0  = (t % 12) * 4;

    // prologue: stage 0
    {
        int k0 = 0;
        #pragma unroll
        for (int it = 0; it < 2; ++it) {
            int kk = a_kk0 + it*8;
            CP_ASYNC16(s_as + (kk*AS_STRIDE + a_m0)*4,
                       aBase + (size_t)(k0+kk)*NPIX + a_m0);
        }
        if (t < 192) {
            CP_ASYNC16(s_bhi + (b_kk*BS_STRIDE + b_n0)*4, &g_Wf_hi[(k0+b_kk)*NP + b_n0]);
            CP_ASYNC16(s_blo + (b_kk*BS_STRIDE + b_n0)*4, &g_Wf_lo[(k0+b_kk)*NP + b_n0]);
        }
        CP_COMMIT();
    }

    float d[6][4];
    #pragma unroll
    for (int nt = 0; nt < 6; ++nt)
        #pragma unroll
        for (int i = 0; i < 4; ++i) d[nt][i] = 0.f;

    for (int kc = 0; kc < NKCH; ++kc) {
        if (kc + 1 < NKCH) {
            int k0 = (kc+1)*BK;
            int p = (kc+1) & 1;
            #pragma unroll
            for (int it = 0; it < 2; ++it) {
                int kk = a_kk0 + it*8;
                CP_ASYNC16(s_as + (p*2176 + kk*AS_STRIDE + a_m0)*4,
                           aBase + (size_t)(k0+kk)*NPIX + a_m0);
            }
            if (t < 192) {
                CP_ASYNC16(s_bhi + (p*896 + b_kk*BS_STRIDE + b_n0)*4, &g_Wf_hi[(k0+b_kk)*NP + b_n0]);
                CP_ASYNC16(s_blo + (p*896 + b_kk*BS_STRIDE + b_n0)*4, &g_Wf_lo[(k0+b_kk)*NP + b_n0]);
            }
            CP_COMMIT();
            asm volatile("cp.async.wait_group 1;\n");
        } else {
            asm volatile("cp.async.wait_group 0;\n");
        }
        __syncthreads();

        const float*    As_ = smem + (kc&1)*2176;
        const uint32_t* Bh  = (const uint32_t*)(smem + 4352) + (kc&1)*896;
        const uint32_t* Bl  = (const uint32_t*)(smem + 6144) + (kc&1)*896;

        #pragma unroll
        for (int ks = 0; ks < 2; ++ks) {
            int kb = ks*8;
            float a0 = As_[(kb+tig  )*AS_STRIDE + wm + gid];
            float a1 = As_[(kb+tig  )*AS_STRIDE + wm + gid + 8];
            float a2 = As_[(kb+tig+4)*AS_STRIDE + wm + gid];
            float a3 = As_[(kb+tig+4)*AS_STRIDE + wm + gid + 8];
            uint32_t ah[4], al[4];
            ah[0] = f2tf32(a0); al[0] = f2tf32(a0 - __uint_as_float(ah[0]));
            ah[1] = f2tf32(a1); al[1] = f2tf32(a1 - __uint_as_float(ah[1]));
            ah[2] = f2tf32(a2); al[2] = f2tf32(a2 - __uint_as_float(ah[2]));
            ah[3] = f2tf32(a3); al[3] = f2tf32(a3 - __uint_as_float(ah[3]));
            #pragma unroll
            for (int nt = 0; nt < 6; ++nt) {
                int n = nt*8 + gid;
                uint32_t bh0 = Bh[(kb+tig  )*BS_STRIDE + n];
                uint32_t bh1 = Bh[(kb+tig+4)*BS_STRIDE + n];
                uint32_t bl0 = Bl[(kb+tig  )*BS_STRIDE + n];
                uint32_t bl1 = Bl[(kb+tig+4)*BS_STRIDE + n];
                mma_tf32(d[nt], ah, bh0, bh1);
                mma_tf32(d[nt], ah, bl0, bl1);
                mma_tf32(d[nt], al, bh0, bh1);
            }
        }
        __syncthreads();
    }

    // stage C into smem, then coalesced write-out with bias add
    float* Cs = smem;
    #pragma unroll
    for (int nt = 0; nt < 6; ++nt) {
        int col = nt*8 + tig*2;
        Cs[(wm + gid    )*NP + col    ] = d[nt][0];
        Cs[(wm + gid    )*NP + col + 1] = d[nt][1];
        Cs[(wm + gid + 8)*NP + col    ] = d[nt][2];
        Cs[(wm + gid + 8)*NP + col + 1] = d[nt][3];
    }
    __syncthreads();
    const float4* csts4 = (const float4*)(smem + 7936);
    float4* outBase = (float4*)(g_pk + (size_t)m0*NP);
    #pragma unroll
    for (int it = 0; it < 6; ++it) {
        int i = t + 256*it;              // 1536 float4 total
        float4 v = ((const float4*)Cs)[i];
        float4 c = csts4[i % 12];
        v.x += c.x; v.y += c.y; v.z += c.z; v.w += c.w;
        outBase[i] = v;
    }
}

// ================= kernel 2: dedupe + routing, one block per (b, instance) =================
__global__ __launch_bounds__(256) void route_kernel(
    const int* __restrict__ pts,
    const float* __restrict__ Wv,       // [258,16] (rel rows 256,257)
    const float* __restrict__ Wl,
    const float* __restrict__ bl,
    float* __restrict__ out)
{
    __shared__ unsigned bitmap[NPIX/32];
    __shared__ int counts[NPIX/32];
    __shared__ int offs[NPIX/32 + 1];
    __shared__ unsigned short cells[NPTS];
    __shared__ int sumY, sumX;
    __shared__ float scores[NCAPS][NPTS];
    __shared__ float vmatS[DV][NPTS];
    __shared__ float qwy[NCAPS], qwx[NCAPS];
    __shared__ float relVy[DV], relVx[DV], Wls[DV];

    int t  = threadIdx.x;
    int bi = blockIdx.x;
    const int* pbase = pts + (size_t)bi*2*NPTS;

    if (t < NPIX/32) bitmap[t] = 0u;
    if (t < NCAPS) { qwy[t] = g_QW[t*258 + 256]; qwx[t] = g_QW[t*258 + 257]; }
    if (t < DV) { relVy[t] = Wv[256*DV + t]; relVx[t] = Wv[257*DV + t]; Wls[t] = Wl[t]; }
    if (t == 0) { sumY = 0; sumX = 0; }
    __syncthreads();

    {
        int y = pbase[t] >> 4;
        int x = pbase[NPTS + t] >> 4;
        int key = y*WFD + x;
        atomicOr(&bitmap[key >> 5], 1u << (key & 31));
    }
    __syncthreads();
    if (t < NPIX/32) counts[t] = __popc(bitmap[t]);
    __syncthreads();
    if (t == 0) {
        int r = 0;
        for (int i = 0; i < NPIX/32; ++i) { offs[i] = r; r += counts[i]; }
        offs[NPIX/32] = r;
    }
    __syncthreads();
    if (t < NPIX/32) {
        unsigned bits = bitmap[t];
        int idx = offs[t];
        int sy = 0, sx = 0;
        while (bits) {
            int bpos = __ffs(bits) - 1;
            bits &= bits - 1;
            int cell = t*32 + bpos;
            cells[idx++] = (unsigned short)cell;
            sy += cell >> 6;
            sx += cell & 63;
        }
        if (counts[t]) { atomicAdd(&sumY, sy); atomicAdd(&sumX, sx); }
    }
    __syncthreads();

    int U = offs[NPIX/32];
    float nfl = (float)(U > 0 ? U : 1);
    float meanY = (float)sumY / nfl;
    float meanX = (float)sumX / nfl;

    if (t < U) {
        int cell = cells[t];
        const float4* pk4 = (const float4*)&g_pk[((size_t)(bi >> 5)*NPIX + cell)*NP];
        float4 q[9];
        #pragma unroll
        for (int i = 0; i < 9; ++i) q[i] = pk4[i];
        const float* pk = (const float*)q;

        float ry = ((float)(cell >> 6) - meanY) * (1.f/HFD);
        float rx = ((float)(cell & 63) - meanX) * (1.f/WFD);
        float act = 1.f/(1.f + expf(-pk[19]));
        float la  = logf(act + 1e-6f);
        #pragma unroll
        for (int c = 0; c < NCAPS; ++c)
            scores[c][t] = pk[c] + ry*qwy[c] + rx*qwx[c] + la;
        #pragma unroll
        for (int dd = 0; dd < DV; ++dd)
            vmatS[dd][t] = pk[20 + dd] + ry*relVy[dd] + rx*relVx[dd];
    }
    __syncthreads();

    int warp = t >> 5, lane = t & 31;
    for (int c = warp; c < NCAPS; c += 8) {
        float mx = -1e30f;
        for (int j = lane; j < U; j += 32) mx = fmaxf(mx, scores[c][j]);
        #pragma unroll
        for (int off = 16; off; off >>= 1) mx = fmaxf(mx, __shfl_xor_sync(0xffffffffu, mx, off));
        float se = 0.f;
        float acc[DV];
        #pragma unroll
        for (int dd = 0; dd < DV; ++dd) acc[dd] = 0.f;
        for (int j = lane; j < U; j += 32) {
            float e = expf(scores[c][j] - mx);
            se += e;
            #pragma unroll
            for (int dd = 0; dd < DV; ++dd) acc[dd] += e*vmatS[dd][j];
        }
        #pragma unroll
        for (int off = 16; off; off >>= 1) {
            se += __shfl_xor_sync(0xffffffffu, se, off);
            #pragma unroll
            for (int dd = 0; dd < DV; ++dd) acc[dd] += __shfl_xor_sync(0xffffffffu, acc[dd], off);
        }
        if (lane == 0) {
            float o = bl[0];
            float inv = 1.f/se;
            #pragma unroll
            for (int dd = 0; dd < DV; ++dd) o += (acc[dd]*inv)*Wls[dd];
            out[bi*NCAPS + c] = 1.f/(1.f + expf(-o));
        }
    }
}

extern "C" void kernel_launch(void* const* d_in, const int* in_sizes, int n_in,
                              void* d_out, int out_size) {
    const float* feat = (const float*)d_in[0];
    const float* Wp   = (const float*)d_in[1];
    const float* bp   = (const float*)d_in[2];
    const float* Wa   = (const float*)d_in[3];
    const float* ba   = (const float*)d_in[4];
    const float* Q    = (const float*)d_in[5];
    const float* Wk   = (const float*)d_in[6];
    const float* bk   = (const float*)d_in[7];
    const float* Wv   = (const float*)d_in[8];
    const float* bv   = (const float*)d_in[9];
    const float* Wl   = (const float*)d_in[10];
    const float* bl   = (const float*)d_in[11];
    const int*   pts  = (const int*)d_in[12];
    float* out = (float*)d_out;

    qw_kernel<<<(NCAPS*258 + 255)/256, 256>>>(Q, Wk);
    fold_kernel<<<CIN, 64>>>(Wp, Wa, Wv);
    const_kernel<<<1, NP>>>(bp, ba, Q, bk, Wv, bv);
    gemm_kernel<<<(BATCH*NPIX)/BM, 256>>>(feat);
    route_kernel<<<BATCH*NINST, 256>>>(pts, Wv, Wl, bl, out);
}